// round 1
// baseline (speedup 1.0000x reference)
#include <cuda_runtime.h>
#include <cstdint>

// Problem constants
#define NTOK   8192        // B*S = 4*2048
#define DMODEL 1024
#define NEXP   8
#define HID    2048
#define TOPK   2
#define TM     128
#define TN     128
#define TKK    8
#define MAXR   (NTOK*TOPK + NEXP*TM)   // 16384 + 1024 = 17408 (per-expert padded to TM)
#define OUT_ELEMS (NTOK*DMODEL)        // 8388608

// ---------------- device scratch (no allocation allowed) ----------------
__device__ int   g_tope[NTOK*2];        // top-2 expert ids per token
__device__ float g_topp[NTOK*2];        // renormalized top-2 probs
__device__ int   g_pos[NTOK*2];         // position of (token,k) in permuted row space
__device__ int   g_perm_tok[MAXR];      // row -> token (-1 = padding)
__device__ int   g_fcount[NEXP];        // argmax counts (aux loss f)
__device__ int   g_scount[NEXP];        // top-2 membership counts
__device__ int   g_off[NEXP+1];         // padded segment offsets
__device__ int   g_cursor[NEXP];        // scatter cursors
__device__ float g_blockP[(NTOK/8)*NEXP]; // per-block partial prob sums (fixed-order reduce)
__device__ float g_hidden[MAXR*HID];    // relu(x @ w1[e])   (~142 MB)
__device__ float g_expout[MAXR*DMODEL]; // hidden @ w2[e]    (~71 MB)

// ---------------- init ----------------
__global__ void init_kernel() {
    int i = blockIdx.x * blockDim.x + threadIdx.x;
    if (i < MAXR) g_perm_tok[i] = -1;
    if (i < NEXP) { g_fcount[i] = 0; g_scount[i] = 0; }
}

// ---------------- router: logits -> softmax -> top2 ----------------
__global__ void __launch_bounds__(256) router_kernel(const float* __restrict__ x,
                                                     const float* __restrict__ gate_w) {
    __shared__ float sg[NEXP * DMODEL];   // 32 KB
    __shared__ float warpP[8][NEXP];
    int tid = threadIdx.x;
    for (int i = tid; i < NEXP * DMODEL; i += 256) sg[i] = gate_w[i];
    __syncthreads();

    int warp = tid >> 5, lane = tid & 31;
    int t = blockIdx.x * 8 + warp;        // one token per warp
    const float* xr = x + (size_t)t * DMODEL;

    float acc[NEXP];
#pragma unroll
    for (int e = 0; e < NEXP; e++) acc[e] = 0.f;
    for (int j = 0; j < DMODEL / 32; j++) {
        float v = xr[j * 32 + lane];
#pragma unroll
        for (int e = 0; e < NEXP; e++) acc[e] += v * sg[e * DMODEL + j * 32 + lane];
    }
#pragma unroll
    for (int e = 0; e < NEXP; e++)
#pragma unroll
        for (int o = 16; o > 0; o >>= 1) acc[e] += __shfl_xor_sync(0xffffffffu, acc[e], o);

    if (lane == 0) {
        float m = acc[0];
#pragma unroll
        for (int e = 1; e < NEXP; e++) m = fmaxf(m, acc[e]);
        float p[NEXP], s = 0.f;
#pragma unroll
        for (int e = 0; e < NEXP; e++) { p[e] = __expf(acc[e] - m); s += p[e]; }
        float inv = 1.f / s;
#pragma unroll
        for (int e = 0; e < NEXP; e++) p[e] *= inv;
        // top-2 (first index wins ties, matching lax.top_k)
        int i1 = 0;
#pragma unroll
        for (int e = 1; e < NEXP; e++) if (p[e] > p[i1]) i1 = e;
        int i2 = (i1 == 0) ? 1 : 0;
#pragma unroll
        for (int e = 0; e < NEXP; e++) if (e != i1 && p[e] > p[i2]) i2 = e;
        float s2 = p[i1] + p[i2];
        g_tope[t * 2 + 0] = i1;  g_topp[t * 2 + 0] = p[i1] / s2;
        g_tope[t * 2 + 1] = i2;  g_topp[t * 2 + 1] = p[i2] / s2;
        atomicAdd(&g_fcount[i1], 1);
        atomicAdd(&g_scount[i1], 1);
        atomicAdd(&g_scount[i2], 1);
#pragma unroll
        for (int e = 0; e < NEXP; e++) warpP[warp][e] = p[e];
    }
    __syncthreads();
    if (tid < NEXP) {
        float s = 0.f;
#pragma unroll
        for (int w = 0; w < 8; w++) s += warpP[w][tid];   // fixed order -> deterministic
        g_blockP[blockIdx.x * NEXP + tid] = s;
    }
}

// ---------------- offsets (1 thread) ----------------
__global__ void offsets_kernel() {
    if (threadIdx.x == 0) {
        int o = 0;
        for (int e = 0; e < NEXP; e++) {
            g_off[e] = o;
            g_cursor[e] = o;
            o += ((g_scount[e] + TM - 1) / TM) * TM;
        }
        g_off[NEXP] = o;
    }
}

// ---------------- scatter tokens into expert buckets ----------------
__global__ void scatter_kernel() {
    int t = blockIdx.x * blockDim.x + threadIdx.x;
    if (t >= NTOK) return;
#pragma unroll
    for (int k = 0; k < 2; k++) {
        int e = g_tope[t * 2 + k];
        int pos = atomicAdd(&g_cursor[e], 1);
        g_perm_tok[pos] = t;
        g_pos[t * 2 + k] = pos;
    }
}

// ---------------- FFMA2 helper ----------------
__device__ __forceinline__ void ffma2(unsigned long long& c, unsigned long long a,
                                      unsigned long long b) {
    asm("fma.rn.f32x2 %0, %1, %2, %0;" : "+l"(c) : "l"(a), "l"(b));
}

// ---------------- GEMM1: hidden = relu(gather(x) @ w1[e]) ----------------
__global__ void __launch_bounds__(256, 2) gemm1_kernel(const float* __restrict__ x,
                                                       const float* __restrict__ w1) {
    __shared__ float As[2][TKK][2 * TM];   // duplicated pairs for f32x2
    __shared__ float Bs[2][TKK][TN];
    __shared__ int   s_tok[TM];

    int row0 = blockIdx.y * TM;
    if (row0 >= g_off[NEXP]) return;
    int e = 0;
#pragma unroll
    for (int q = 1; q < NEXP; q++) if (row0 >= g_off[q]) e = q;
    const float* B = w1 + (size_t)e * DMODEL * HID;
    int bn0 = blockIdx.x * TN;
    int tid = threadIdx.x;
    if (tid < TM) s_tok[tid] = g_perm_tok[row0 + tid];
    __syncthreads();

    int ar = tid >> 1, ak = (tid & 1) * 4;
    int bk = tid >> 5, bn = (tid & 31) * 4;
    int tx = tid & 15, ty = tid >> 4;
    int tokA = s_tok[ar];
    const float* Arow = (tokA >= 0) ? (x + (size_t)tokA * DMODEL + ak) : x;

    unsigned long long acc[8][4];
#pragma unroll
    for (int i = 0; i < 8; i++)
#pragma unroll
        for (int j = 0; j < 4; j++) acc[i][j] = 0ull;

    // prologue: tile 0
    {
        float4 av = make_float4(0.f, 0.f, 0.f, 0.f);
        if (tokA >= 0) av = *(const float4*)(Arow + 0);
        *(float2*)&As[0][ak + 0][2 * ar] = make_float2(av.x, av.x);
        *(float2*)&As[0][ak + 1][2 * ar] = make_float2(av.y, av.y);
        *(float2*)&As[0][ak + 2][2 * ar] = make_float2(av.z, av.z);
        *(float2*)&As[0][ak + 3][2 * ar] = make_float2(av.w, av.w);
        float4 bv = *(const float4*)(B + (size_t)bk * HID + bn0 + bn);
        *(float4*)&Bs[0][bk][bn] = bv;
    }
    __syncthreads();

    const int nk = DMODEL / TKK;   // 128
    for (int kt = 0; kt < nk; kt++) {
        int buf = kt & 1;
        float4 av2, bv2;
        bool more = (kt + 1 < nk);
        if (more) {
            av2 = make_float4(0.f, 0.f, 0.f, 0.f);
            if (tokA >= 0) av2 = *(const float4*)(Arow + (kt + 1) * TKK);
            bv2 = *(const float4*)(B + (size_t)((kt + 1) * TKK + bk) * HID + bn0 + bn);
        }
#pragma unroll
        for (int kk = 0; kk < TKK; kk++) {
            unsigned long long a8[8], b4[4];
#pragma unroll
            for (int i = 0; i < 8; i++)
                a8[i] = *(const unsigned long long*)&As[buf][kk][2 * (ty * 8 + i)];
#pragma unroll
            for (int j = 0; j < 4; j++)
                b4[j] = *(const unsigned long long*)&Bs[buf][kk][tx * 8 + 2 * j];
#pragma unroll
            for (int i = 0; i < 8; i++)
#pragma unroll
                for (int j = 0; j < 4; j++) ffma2(acc[i][j], a8[i], b4[j]);
        }
        if (more) {
            int nb = buf ^ 1;
            *(float2*)&As[nb][ak + 0][2 * ar] = make_float2(av2.x, av2.x);
            *(float2*)&As[nb][ak + 1][2 * ar] = make_float2(av2.y, av2.y);
            *(float2*)&As[nb][ak + 2][2 * ar] = make_float2(av2.z, av2.z);
            *(float2*)&As[nb][ak + 3][2 * ar] = make_float2(av2.w, av2.w);
            *(float4*)&Bs[nb][bk][bn] = bv2;
            __syncthreads();
        }
    }

    // epilogue: relu + store
#pragma unroll
    for (int i = 0; i < 8; i++) {
        int row = row0 + ty * 8 + i;
        float* dst = g_hidden + (size_t)row * HID + bn0 + tx * 8;
#pragma unroll
        for (int j = 0; j < 4; j++) {
            float2 v = *(float2*)&acc[i][j];
            v.x = fmaxf(v.x, 0.f);
            v.y = fmaxf(v.y, 0.f);
            *(float2*)(dst + 2 * j) = v;
        }
    }
}

// ---------------- GEMM2: expout = hidden @ w2[e] ----------------
__global__ void __launch_bounds__(256, 2) gemm2_kernel(const float* __restrict__ w2) {
    __shared__ float As[2][TKK][2 * TM];
    __shared__ float Bs[2][TKK][TN];

    int row0 = blockIdx.y * TM;
    if (row0 >= g_off[NEXP]) return;
    int e = 0;
#pragma unroll
    for (int q = 1; q < NEXP; q++) if (row0 >= g_off[q]) e = q;
    const float* B = w2 + (size_t)e * HID * DMODEL;
    int bn0 = blockIdx.x * TN;
    int tid = threadIdx.x;

    int ar = tid >> 1, ak = (tid & 1) * 4;
    int bk = tid >> 5, bn = (tid & 31) * 4;
    int tx = tid & 15, ty = tid >> 4;
    const float* Arow = g_hidden + (size_t)(row0 + ar) * HID + ak;

    unsigned long long acc[8][4];
#pragma unroll
    for (int i = 0; i < 8; i++)
#pragma unroll
        for (int j = 0; j < 4; j++) acc[i][j] = 0ull;

    {
        float4 av = *(const float4*)(Arow + 0);
        *(float2*)&As[0][ak + 0][2 * ar] = make_float2(av.x, av.x);
        *(float2*)&As[0][ak + 1][2 * ar] = make_float2(av.y, av.y);
        *(float2*)&As[0][ak + 2][2 * ar] = make_float2(av.z, av.z);
        *(float2*)&As[0][ak + 3][2 * ar] = make_float2(av.w, av.w);
        float4 bv = *(const float4*)(B + (size_t)bk * DMODEL + bn0 + bn);
        *(float4*)&Bs[0][bk][bn] = bv;
    }
    __syncthreads();

    const int nk = HID / TKK;   // 256
    for (int kt = 0; kt < nk; kt++) {
        int buf = kt & 1;
        float4 av2, bv2;
        bool more = (kt + 1 < nk);
        if (more) {
            av2 = *(const float4*)(Arow + (kt + 1) * TKK);
            bv2 = *(const float4*)(B + (size_t)((kt + 1) * TKK + bk) * DMODEL + bn0 + bn);
        }
#pragma unroll
        for (int kk = 0; kk < TKK; kk++) {
            unsigned long long a8[8], b4[4];
#pragma unroll
            for (int i = 0; i < 8; i++)
                a8[i] = *(const unsigned long long*)&As[buf][kk][2 * (ty * 8 + i)];
#pragma unroll
            for (int j = 0; j < 4; j++)
                b4[j] = *(const unsigned long long*)&Bs[buf][kk][tx * 8 + 2 * j];
#pragma unroll
            for (int i = 0; i < 8; i++)
#pragma unroll
                for (int j = 0; j < 4; j++) ffma2(acc[i][j], a8[i], b4[j]);
        }
        if (more) {
            int nb = buf ^ 1;
            *(float2*)&As[nb][ak + 0][2 * ar] = make_float2(av2.x, av2.x);
            *(float2*)&As[nb][ak + 1][2 * ar] = make_float2(av2.y, av2.y);
            *(float2*)&As[nb][ak + 2][2 * ar] = make_float2(av2.z, av2.z);
            *(float2*)&As[nb][ak + 3][2 * ar] = make_float2(av2.w, av2.w);
            *(float4*)&Bs[nb][bk][bn] = bv2;
            __syncthreads();
        }
    }

#pragma unroll
    for (int i = 0; i < 8; i++) {
        int row = row0 + ty * 8 + i;
        float* dst = g_expout + (size_t)row * DMODEL + bn0 + tx * 8;
#pragma unroll
        for (int j = 0; j < 4; j++) {
            float2 v = *(float2*)&acc[i][j];
            *(float2*)(dst + 2 * j) = v;
        }
    }
}

// ---------------- combine: out[t] = p0*expout[pos0] + p1*expout[pos1] ----------------
__global__ void combine_kernel(float* __restrict__ out) {
    int idx = blockIdx.x * blockDim.x + threadIdx.x;   // over NTOK * (DMODEL/4)
    if (idx >= NTOK * (DMODEL / 4)) return;
    int t = idx >> 8;         // DMODEL/4 = 256
    int c = idx & 255;
    float p0 = g_topp[t * 2 + 0], p1 = g_topp[t * 2 + 1];
    size_t r0 = (size_t)g_pos[t * 2 + 0] * (DMODEL / 4);
    size_t r1 = (size_t)g_pos[t * 2 + 1] * (DMODEL / 4);
    const float4* buf = (const float4*)g_expout;
    float4 a = buf[r0 + c];
    float4 b = buf[r1 + c];
    float4 o;
    o.x = p0 * a.x + p1 * b.x;
    o.y = p0 * a.y + p1 * b.y;
    o.z = p0 * a.z + p1 * b.z;
    o.w = p0 * a.w + p1 * b.w;
    ((float4*)out)[idx] = o;
}

// ---------------- aux loss ----------------
__global__ void aux_kernel(float* __restrict__ out, int out_size) {
    __shared__ float P[NEXP];
    int e = threadIdx.x;
    if (e < NEXP) {
        float s = 0.f;
        for (int b = 0; b < NTOK / 8; b++) s += g_blockP[b * NEXP + e];  // fixed order
        P[e] = s * (1.0f / NTOK);
    }
    __syncthreads();
    if (threadIdx.x == 0 && out_size > OUT_ELEMS) {
        float aux = 0.f;
        for (int q = 0; q < NEXP; q++)
            aux += ((float)g_fcount[q] * (1.0f / NTOK)) * P[q];
        aux *= 0.01f * NEXP;
        out[OUT_ELEMS] = aux;
    }
}

// ---------------- launch ----------------
extern "C" void kernel_launch(void* const* d_in, const int* in_sizes, int n_in,
                              void* d_out, int out_size) {
    const float* x      = (const float*)d_in[0];
    const float* gate_w = (const float*)d_in[1];
    const float* w1     = (const float*)d_in[2];
    const float* w2     = (const float*)d_in[3];
    float* out = (float*)d_out;

    init_kernel<<<(MAXR + 255) / 256, 256>>>();
    router_kernel<<<NTOK / 8, 256>>>(x, gate_w);
    offsets_kernel<<<1, 32>>>();
    scatter_kernel<<<(NTOK + 255) / 256, 256>>>();

    dim3 g1(HID / TN, MAXR / TM);      // (16, 136)
    gemm1_kernel<<<g1, 256>>>(x, w1);
    dim3 g2(DMODEL / TN, MAXR / TM);   // (8, 136)
    gemm2_kernel<<<g2, 256>>>(w2);

    combine_kernel<<<(NTOK * (DMODEL / 4) + 255) / 256, 256>>>(out);
    aux_kernel<<<1, 32>>>(out, out_size);
}